// round 15
// baseline (speedup 1.0000x reference)
#include <cuda_runtime.h>
#include <cstdint>

// naivePC: DP over (k,m) lattice, K=8, N=20.
// Transformed DP: S~(k,m) = S(k,m)/P_k[m]; one predicated FFMA per (level, column).
// Leaf/k2 collapse: cc = v*invP2[mstart], injection via Q bitmask (see prior rounds).
// Structure: persistent warps, grid-stride over 32-row tiles, register double buffer
// with prefetch distance 2 (ballots free the buffer, loads refill it, DP covers latency).

#define NCOL 20
#define KMAX 8
#define THREADS 128
#define BLOCKS 592            // 4 blocks/SM * 148 SMs: exactly one wave

__device__ float  g_wsm[21 * 32];
__device__ float2 g_w01[9 * 21];
__device__ float  g_invP2[22];
__device__ float4 g_gA[21];    // (g3t, g4, g5, g6)
__device__ float2 g_gB[21];    // (g7, g8)
__device__ float  g_scale;     // P_8[20]
__device__ int    g_elem4;

__global__ void prep_kernel(const unsigned char* __restrict__ xb,
                            const float* __restrict__ Wleaf,
                            const float* __restrict__ W2)
{
    __shared__ float sP[9][21];

    const int tid  = threadIdx.x;
    const int lane = tid & 31;
    const int wid  = tid >> 5;

    if (wid < 21) {
        int m = wid;
        float v = (lane < m) ? Wleaf[m * 20 + lane] : -1e30f;
        float mx = v;
        #pragma unroll
        for (int o = 16; o > 0; o >>= 1) mx = fmaxf(mx, __shfl_xor_sync(0xFFFFFFFFu, mx, o));
        float e = (lane < m) ? expf(v - mx) : 0.0f;
        float Z = e;
        #pragma unroll
        for (int o = 16; o > 0; o >>= 1) Z += __shfl_xor_sync(0xFFFFFFFFu, Z, o);
        float inv = (m > 0) ? (1.0f / Z) : 0.0f;
        g_wsm[m * 32 + lane] = e * inv;
    }
    if (tid < 9 * 21) {
        float a = W2[tid * 2 + 0];
        float b = W2[tid * 2 + 1];
        float mx = fmaxf(a, b);
        float e0 = expf(a - mx), e1 = expf(b - mx);
        float inv = 1.0f / (e0 + e1);
        g_w01[tid] = make_float2(e0 * inv, e1 * inv);
    }
    if (wid == 21) {
        unsigned w = reinterpret_cast<const unsigned*>(xb)[lane];
        unsigned gt1 = __ballot_sync(0xFFFFFFFFu, (w & 0xFEFEFEFEu) != 0u);
        unsigned hi  = __ballot_sync(0xFFFFFFFFu, (w & 0xFFFFFF00u) != 0u);
        if (lane == 0) g_elem4 = (gt1 != 0u || hi == 0u) ? 1 : 0;
    }
    __syncthreads();

    if (tid >= 2 && tid <= 8) {
        int k = tid;
        float p = 1.0f;
        for (int m = k; m <= 20; m++) {
            if (m > k) p *= g_w01[k * 21 + m].x;
            sP[k][m] = p;
        }
    }
    __syncthreads();

    if (tid < 21) {
        int m = tid;
        g_invP2[m] = (m >= 2) ? (1.0f / sP[2][m]) : 0.0f;
        float4 a;
        float2 b;
        a.x = (m >= 4) ? g_w01[3 * 21 + m].y * sP[2][m - 1] / sP[3][m] : 0.0f;
        a.y = (m >= 5) ? g_w01[4 * 21 + m].y * sP[3][m - 1] / sP[4][m] : 0.0f;
        a.z = (m >= 6) ? g_w01[5 * 21 + m].y * sP[4][m - 1] / sP[5][m] : 0.0f;
        a.w = (m >= 7) ? g_w01[6 * 21 + m].y * sP[5][m - 1] / sP[6][m] : 0.0f;
        b.x = (m >= 8) ? g_w01[7 * 21 + m].y * sP[6][m - 1] / sP[7][m] : 0.0f;
        b.y = (m >= 9) ? g_w01[8 * 21 + m].y * sP[7][m - 1] / sP[8][m] : 0.0f;
        g_gA[m] = a;
        g_gB[m] = b;
    }
    if (tid == 21) { g_invP2[21] = 0.0f; g_scale = sP[8][20]; }
}

// ---- load one 32-row tile's 20 word-columns (guarded) ----
__device__ __forceinline__ void load_tile(const unsigned* __restrict__ xw,
                                          unsigned (&w)[20],
                                          int t, int NT, int B, int wTotal, int lane)
{
    if (t >= NT) return;
    const int base = t * 640 + lane;
    if (t * 32 + 32 <= B) {
        #pragma unroll
        for (int j = 0; j < 20; j++) w[j] = __ldg(xw + base + j * 32);
    } else {
        #pragma unroll
        for (int j = 0; j < 20; j++) {
            int idx = base + j * 32;
            w[j] = (idx < wTotal) ? __ldg(xw + idx) : 0u;
        }
    }
}

// ---- process one tile: ballots, prefetch, extract, leaf collapse, DP, store ----
__device__ __forceinline__ void process_tile(const unsigned* __restrict__ xw,
                                             unsigned (&w)[20],
                                             int t, int tpre,
                                             int NT, int B, int wTotal,
                                             int lane, unsigned* __restrict__ sbal,
                                             float scale,
                                             float* __restrict__ out)
{
    // 1. ballots consume w (each result is warp-uniform)
    #pragma unroll
    for (int j = 0; j < 20; j++) {
        unsigned bal = __ballot_sync(0xFFFFFFFFu, w[j] != 0u);
        if (lane == 0) sbal[j] = bal;
    }
    // 2. refill w for tile tpre (prefetch distance 2)
    load_tile(xw, w, tpre, NT, B, wTotal, lane);
    __syncwarp();

    // 3. extract this lane's 20-bit row mask
    const int pos = 20 * lane;
    unsigned lo = sbal[pos >> 5];
    unsigned hi = sbal[(pos >> 5) + 1];
    unsigned M = __funnelshift_r(lo, hi, pos & 31) & 0xFFFFFu;

    // 4. leaf/k2 collapse
    unsigned rem = M & (M - 1);
    int mst;
    float v;
    if (rem != 0u) {
        int p1 = __ffs(M) - 1;
        int p2 = __ffs(rem) - 1;
        mst = p2 + 1;
        bool pf2 = (M & 3u) == 3u;
        v = pf2 ? 1.0f : __ldg(&((const float*)g_w01)[(2 * 21 + mst) * 2 + 1])
                       * __ldg(&g_wsm[p2 * 32 + p1]);
    } else {
        mst = 21;
        v = 0.0f;
    }
    const float cc = v * __ldg(&g_invP2[mst]);
    const unsigned Q = M & (0xFFFFFFFFu << mst);

    // 5. column-sweep DP, levels k=3..8
    float S[KMAX - 2];
    #pragma unroll
    for (int k = 0; k < KMAX - 2; k++) S[k] = 0.0f;

    #pragma unroll
    for (int m = 1; m <= NCOL; m++) {
        const unsigned mbit = 1u << (m - 1);
        const float4 ga = __ldg(&g_gA[m]);
        const float2 gb = __ldg(&g_gB[m]);

        #pragma unroll
        for (int k = KMAX; k >= 4; k--) {
            if (k > m) continue;                    // folds at compile time
            if (k == m) {
                const unsigned km = (1u << k) - 1u;
                S[k - 3] = ((M & km) == km) ? 1.0f : 0.0f;
            } else {
                const float g = (k == 4) ? ga.y : (k == 5) ? ga.z : (k == 6) ? ga.w
                              : (k == 7) ? gb.x : gb.y;
                S[k - 3] = (M & mbit) ? fmaf(g, S[k - 4], S[k - 3]) : S[k - 3];
            }
        }
        if (m == 3) {
            S[0] = ((M & 7u) == 7u) ? 1.0f : 0.0f;
        } else if (m > 3) {
            S[0] = (Q & mbit) ? fmaf(ga.x, cc, S[0]) : S[0];
        }
    }

    // 6. coalesced store
    int row = t * 32 + lane;
    if (row < B) out[row] = S[KMAX - 3] * scale;
}

__global__ __launch_bounds__(THREADS, 4)
void pc_kernel(const unsigned char* __restrict__ xb,
               float* __restrict__ out,
               int B)
{
    __shared__ unsigned s_bal[THREADS / 32][24];

    const int tid    = threadIdx.x;
    const int lane   = tid & 31;
    const int warpId = tid >> 5;
    const int elem4  = g_elem4;

    const int NT = (B + 31) >> 5;                       // number of 32-row tiles
    const int nw = (gridDim.x * THREADS) >> 5;          // total warps (2368)
    const int wg = (blockIdx.x * THREADS + tid) >> 5;   // this warp's id
    const int wTotal = B * 20;
    const float scale = __ldg(&g_scale);

    if (elem4) {
        const unsigned* xw = reinterpret_cast<const unsigned*>(xb);
        unsigned wA[20], wB[20];
        int t = wg;
        load_tile(xw, wA, t, NT, B, wTotal, lane);
        load_tile(xw, wB, t + nw, NT, B, wTotal, lane);
        while (t < NT) {
            process_tile(xw, wA, t, t + 2 * nw, NT, B, wTotal, lane,
                         s_bal[warpId], scale, out);
            t += nw;
            if (t >= NT) break;
            process_tile(xw, wB, t, t + 2 * nw, NT, B, wTotal, lane,
                         s_bal[warpId], scale, out);
            t += nw;
        }
    } else {
        // bool-byte path: per-lane row masks, grid-stride (correctness fallback)
        for (int t = wg; t < NT; t += nw) {
            int row = t * 32 + lane;
            unsigned M = 0;
            if (row < B) {
                const unsigned* p = reinterpret_cast<const unsigned*>(xb + (size_t)row * 20);
                #pragma unroll
                for (int j = 0; j < 5; j++) {
                    unsigned b = p[j] & 0x01010101u;
                    unsigned nib = ((b * 0x01020408u) >> 24) & 0xFu;
                    M |= nib << (4 * j);
                }
            }
            // leaf collapse + DP (same as process_tile steps 4-6)
            unsigned rem = M & (M - 1);
            int mst; float v;
            if (rem != 0u) {
                int p1 = __ffs(M) - 1;
                int p2 = __ffs(rem) - 1;
                mst = p2 + 1;
                bool pf2 = (M & 3u) == 3u;
                v = pf2 ? 1.0f : __ldg(&((const float*)g_w01)[(2 * 21 + mst) * 2 + 1])
                               * __ldg(&g_wsm[p2 * 32 + p1]);
            } else { mst = 21; v = 0.0f; }
            const float cc = v * __ldg(&g_invP2[mst]);
            const unsigned Q = M & (0xFFFFFFFFu << mst);

            float S[KMAX - 2];
            #pragma unroll
            for (int k = 0; k < KMAX - 2; k++) S[k] = 0.0f;
            #pragma unroll
            for (int m = 1; m <= NCOL; m++) {
                const unsigned mbit = 1u << (m - 1);
                const float4 ga = __ldg(&g_gA[m]);
                const float2 gb = __ldg(&g_gB[m]);
                #pragma unroll
                for (int k = KMAX; k >= 4; k--) {
                    if (k > m) continue;
                    if (k == m) {
                        const unsigned km = (1u << k) - 1u;
                        S[k - 3] = ((M & km) == km) ? 1.0f : 0.0f;
                    } else {
                        const float g = (k == 4) ? ga.y : (k == 5) ? ga.z : (k == 6) ? ga.w
                                      : (k == 7) ? gb.x : gb.y;
                        S[k - 3] = (M & mbit) ? fmaf(g, S[k - 4], S[k - 3]) : S[k - 3];
                    }
                }
                if (m == 3) S[0] = ((M & 7u) == 7u) ? 1.0f : 0.0f;
                else if (m > 3) S[0] = (Q & mbit) ? fmaf(ga.x, cc, S[0]) : S[0];
            }
            if (row < B) out[row] = S[KMAX - 3] * scale;
        }
    }
}

extern "C" void kernel_launch(void* const* d_in, const int* in_sizes, int n_in,
                              void* d_out, int out_size)
{
    const unsigned char* x = (const unsigned char*)d_in[0];
    const float* Wleaf = (const float*)d_in[1];
    const float* W2 = (const float*)d_in[2];
    float* out = (float*)d_out;

    const int B = in_sizes[0] / NCOL;

    prep_kernel<<<1, 736>>>(x, Wleaf, W2);
    pc_kernel<<<BLOCKS, THREADS>>>(x, out, B);
}